// round 2
// baseline (speedup 1.0000x reference)
#include <cuda_runtime.h>
#include <math.h>

#define NMAX 50000
#define EMAX 800000

// ---------------- scratch (static device globals; no allocation) ----------------
__device__ __align__(16) int   g_src[EMAX];
__device__ __align__(16) int   g_dst[EMAX];
__device__ __align__(16) float g_xp1[NMAX * 128];   // layer-1 features; holds h after fin1
__device__ __align__(16) float g_num1[NMAX * 128];
__device__ __align__(16) float g_xp2[NMAX * 64];
__device__ __align__(16) float g_num2[NMAX * 64];
__device__ __align__(16) float g_as1[NMAX * 2], g_ad1[NMAX * 2], g_em1[NMAX * 2], g_dn1[NMAX * 2];
__device__ __align__(16) float g_as2[NMAX * 2], g_ad2[NMAX * 2], g_em2[NMAX * 2], g_dn2[NMAX * 2];
__device__ int g_is64;

// layer-selected buffer accessors (device code may decay __device__ arrays to pointers)
template <int L> __device__ __forceinline__ float* XP()  { return L == 1 ? g_xp1  : g_xp2;  }
template <int L> __device__ __forceinline__ float* NUM() { return L == 1 ? g_num1 : g_num2; }
template <int L> __device__ __forceinline__ float* AS()  { return L == 1 ? g_as1  : g_as2;  }
template <int L> __device__ __forceinline__ float* AD()  { return L == 1 ? g_ad1  : g_ad2;  }
template <int L> __device__ __forceinline__ float* EM()  { return L == 1 ? g_em1  : g_em2;  }
template <int L> __device__ __forceinline__ float* DN()  { return L == 1 ? g_dn1  : g_dn2;  }

__device__ __forceinline__ float lrelu(float x) { return x > 0.f ? x : 0.2f * x; }

// Correct float atomic max: int-max for non-negative, unsigned-min for negative.
__device__ __forceinline__ void atomicMaxF(float* a, float v) {
    if (v >= 0.f) atomicMax((int*)a, __float_as_int(v));
    else          atomicMin((unsigned int*)a, (unsigned int)__float_as_int(v));
}

// ---------------- kernels ----------------

// Detect whether edge_index is int64 (odd int32 words all zero) or int32.
__global__ void k_detect(const int* __restrict__ ei32) {
    __shared__ int any;
    if (threadIdx.x == 0) any = 0;
    __syncthreads();
    for (int i = threadIdx.x; i < 2048; i += blockDim.x)
        if (ei32[2 * i + 1] != 0) any = 1;
    __syncthreads();
    if (threadIdx.x == 0) g_is64 = (any == 0) ? 1 : 0;
}

__global__ void k_convert(const void* __restrict__ ei, int E) {
    int e = blockIdx.x * blockDim.x + threadIdx.x;
    if (e >= E) return;
    if (g_is64) {
        const long long* p = (const long long*)ei;
        g_src[e] = (int)p[e];
        g_dst[e] = (int)p[(size_t)E + e];
    } else {
        const int* p = (const int*)ei;
        g_src[e] = p[e];
        g_dst[e] = p[(size_t)E + e];
    }
}

// Y[n, NCOL] = X[n,128] @ W[128, NCOL].  Block: NCOL threads, 32 rows per block.
template <int L>
__global__ void k_gemm(const float* __restrict__ Xin, const float* __restrict__ W, int n) {
    constexpr int NCOL = (L == 1) ? 128 : 64;
    const float* X = (L == 1) ? Xin : g_xp1;
    float*       Y = XP<L>();
    __shared__ float Ws[64][NCOL];
    __shared__ float Xs[32][64];
    int t  = threadIdx.x;
    int n0 = blockIdx.x * 32;
    float acc[32];
#pragma unroll
    for (int i = 0; i < 32; i++) acc[i] = 0.f;

    for (int kt = 0; kt < 128; kt += 64) {
        for (int k = 0; k < 64; k++) Ws[k][t] = W[(size_t)(kt + k) * NCOL + t];
        for (int i = t; i < 32 * 64; i += NCOL) {
            int nn = i >> 6, kk = i & 63;
            int row = n0 + nn;
            Xs[nn][kk] = (row < n) ? X[(size_t)row * 128 + kt + kk] : 0.f;
        }
        __syncthreads();
#pragma unroll 4
        for (int k = 0; k < 64; k++) {
            float w = Ws[k][t];
#pragma unroll
            for (int nn = 0; nn < 32; nn++) acc[nn] += Xs[nn][k] * w;
        }
        __syncthreads();
    }
#pragma unroll
    for (int nn = 0; nn < 32; nn++) {
        int row = n0 + nn;
        if (row < n) Y[(size_t)row * NCOL + t] = acc[nn];
    }
}

// Per-node attention dots; also seeds emax with the self-loop logit.
template <int L>
__global__ void k_att(const float* __restrict__ att_s, const float* __restrict__ att_d, int n) {
    constexpr int C = (L == 1) ? 128 : 64;
    const float* xp = XP<L>();
    float *as_ = AS<L>(), *ad_ = AD<L>(), *em_ = EM<L>();
    int w    = (int)((blockIdx.x * blockDim.x + threadIdx.x) >> 5);
    int lane = threadIdx.x & 31;
    if (w >= n) return;
    const float* row = xp + (size_t)w * C;
    float s0 = 0.f, s1 = 0.f, d0 = 0.f, d1 = 0.f;
#pragma unroll
    for (int i = 0; i < C / 32; i++) {
        int c   = lane + 32 * i;
        float v = row[c];
        float ts = v * att_s[c], td = v * att_d[c];
        if (c < C / 2) { s0 += ts; d0 += td; } else { s1 += ts; d1 += td; }
    }
#pragma unroll
    for (int o = 16; o; o >>= 1) {
        s0 += __shfl_xor_sync(0xffffffffu, s0, o);
        s1 += __shfl_xor_sync(0xffffffffu, s1, o);
        d0 += __shfl_xor_sync(0xffffffffu, d0, o);
        d1 += __shfl_xor_sync(0xffffffffu, d1, o);
    }
    if (lane == 0) {
        as_[2 * w] = s0;  as_[2 * w + 1] = s1;
        ad_[2 * w] = d0;  ad_[2 * w + 1] = d1;
        em_[2 * w]     = lrelu(s0 + d0);       // self-loop logit seeds segment max
        em_[2 * w + 1] = lrelu(s1 + d1);
    }
}

template <int L>
__global__ void k_edge_max(int E) {
    const float *as_ = AS<L>(), *ad_ = AD<L>();
    float* em_ = EM<L>();
    int e = blockIdx.x * blockDim.x + threadIdx.x;
    if (e >= E) return;
    int s = g_src[e], d = g_dst[e];
    float2 a = *(const float2*)(as_ + 2 * (size_t)s);
    float2 b = *(const float2*)(ad_ + 2 * (size_t)d);
    atomicMaxF(&em_[2 * (size_t)d],     lrelu(a.x + b.x));
    atomicMaxF(&em_[2 * (size_t)d + 1], lrelu(a.y + b.y));
}

// Initialize denom and numerator with the self-loop term (no atomics needed).
template <int L>
__global__ void k_selfinit(int n) {
    constexpr int C = (L == 1) ? 128 : 64;
    const float *xp = XP<L>(), *as_ = AS<L>(), *ad_ = AD<L>(), *em_ = EM<L>();
    float *dn_ = DN<L>(), *num_ = NUM<L>();
    int w    = (int)((blockIdx.x * blockDim.x + threadIdx.x) >> 5);
    int lane = threadIdx.x & 31;
    if (w >= n) return;
    float e0  = lrelu(as_[2 * w] + ad_[2 * w]);
    float e1  = lrelu(as_[2 * w + 1] + ad_[2 * w + 1]);
    float ee0 = __expf(e0 - em_[2 * w]);
    float ee1 = __expf(e1 - em_[2 * w + 1]);
    if (lane == 0) { dn_[2 * w] = ee0; dn_[2 * w + 1] = ee1; }
    const float4* xr = (const float4*)(xp + (size_t)w * C);
    float4*       nr = (float4*)(num_ + (size_t)w * C);
#pragma unroll
    for (int i = lane; i < C / 4; i += 32) {
        float ee = (4 * i < C / 2) ? ee0 : ee1;
        float4 v = xr[i];
        nr[i] = make_float4(v.x * ee, v.y * ee, v.z * ee, v.w * ee);
    }
}

// Fused edge pass: recompute logit, exp, atomic denom, vector-red numerator.
template <int L>
__global__ void k_scatter(int E) {
    constexpr int C   = (L == 1) ? 128 : 64;
    constexpr int Q   = C / 4;   // float4 slots per edge (32 or 16)
    constexpr int EPW = 32 / Q;  // edges per warp (1 or 2)
    const float *xp = XP<L>(), *as_ = AS<L>(), *ad_ = AD<L>(), *em_ = EM<L>();
    float *dn_ = DN<L>(), *num_ = NUM<L>();
    int gw   = (int)((blockIdx.x * blockDim.x + threadIdx.x) >> 5);
    int lane = threadIdx.x & 31;
    int e    = gw * EPW + lane / Q;
    int li   = lane % Q;
    if (e >= E) return;
    int s = g_src[e], d = g_dst[e];
    int head = (4 * li >= C / 2) ? 1 : 0;
    float ev = lrelu(as_[2 * (size_t)s + head] + ad_[2 * (size_t)d + head]);
    float ee = __expf(ev - em_[2 * (size_t)d + head]);
    if ((li & (Q / 2 - 1)) == 0) atomicAdd(&dn_[2 * (size_t)d + head], ee);
    float4 v = *(const float4*)(xp + (size_t)s * C + 4 * li);
    float* np = num_ + (size_t)d * C + 4 * li;
    asm volatile("red.global.add.v4.f32 [%0], {%1,%2,%3,%4};"
                 :: "l"(np), "f"(v.x * ee), "f"(v.y * ee), "f"(v.z * ee), "f"(v.w * ee)
                 : "memory");
}

// h = elu(num/denom + b1)  -> overwrites g_xp1
__global__ void k_fin1(const float* __restrict__ b, int n) {
    int i = blockIdx.x * blockDim.x + threadIdx.x;  // float4 slot over n*32
    if (i >= n * 32) return;
    int node = i >> 5, q = i & 31;
    int head = q >> 4;
    float inv = 1.f / g_dn1[2 * (size_t)node + head];
    float4 v  = *(const float4*)(g_num1 + ((size_t)node << 7) + 4 * q);
    float4 bb = *(const float4*)(b + 4 * q);
    float4 r;
    r.x = v.x * inv + bb.x; r.x = r.x > 0.f ? r.x : expm1f(r.x);
    r.y = v.y * inv + bb.y; r.y = r.y > 0.f ? r.y : expm1f(r.y);
    r.z = v.z * inv + bb.z; r.z = r.z > 0.f ? r.z : expm1f(r.z);
    r.w = v.w * inv + bb.w; r.w = r.w > 0.f ? r.w : expm1f(r.w);
    *(float4*)(g_xp1 + ((size_t)node << 7) + 4 * q) = r;
}

// out = log_softmax(num/denom + b2) over 64 channels; one warp per node.
__global__ void k_fin2(const float* __restrict__ b, float* __restrict__ out, int n) {
    int w    = (int)((blockIdx.x * blockDim.x + threadIdx.x) >> 5);
    int lane = threadIdx.x & 31;
    if (w >= n) return;
    float inv0 = 1.f / g_dn2[2 * (size_t)w], inv1 = 1.f / g_dn2[2 * (size_t)w + 1];
    int c0 = 2 * lane, c1 = c0 + 1;
    float inv = (c0 < 32) ? inv0 : inv1;
    float2 v = *(const float2*)(g_num2 + (size_t)w * 64 + c0);
    float z0 = v.x * inv + b[c0];
    float z1 = v.y * inv + b[c1];
    float m = fmaxf(z0, z1);
#pragma unroll
    for (int o = 16; o; o >>= 1) m = fmaxf(m, __shfl_xor_sync(0xffffffffu, m, o));
    float se = expf(z0 - m) + expf(z1 - m);
#pragma unroll
    for (int o = 16; o; o >>= 1) se += __shfl_xor_sync(0xffffffffu, se, o);
    float lse = m + logf(se);
    *(float2*)(out + (size_t)w * 64 + c0) = make_float2(z0 - lse, z1 - lse);
}

// ---------------- host ----------------
extern "C" void kernel_launch(void* const* d_in, const int* in_sizes, int n_in,
                              void* d_out, int out_size) {
    const float* x   = (const float*)d_in[0];
    const void*  ei  = d_in[1];
    const float* W1  = (const float*)d_in[2];
    const float* a1s = (const float*)d_in[3];
    const float* a1d = (const float*)d_in[4];
    const float* b1  = (const float*)d_in[5];
    const float* W2  = (const float*)d_in[6];
    const float* a2s = (const float*)d_in[7];
    const float* a2d = (const float*)d_in[8];
    const float* b2  = (const float*)d_in[9];
    float* out = (float*)d_out;

    int n = in_sizes[0] / 128;
    int E = in_sizes[1] / 2;

    k_detect<<<1, 256>>>((const int*)ei);
    k_convert<<<(E + 255) / 256, 256>>>(ei, E);

    // ---- layer 1 (C = 128) ----
    k_gemm<1><<<(n + 31) / 32, 128>>>(x, W1, n);
    k_att<1><<<(n + 7) / 8, 256>>>(a1s, a1d, n);
    k_edge_max<1><<<(E + 255) / 256, 256>>>(E);
    k_selfinit<1><<<(n + 7) / 8, 256>>>(n);
    k_scatter<1><<<(E + 7) / 8, 256>>>(E);
    k_fin1<<<(n * 32 + 255) / 256, 256>>>(b1, n);

    // ---- layer 2 (C = 64) ----
    k_gemm<2><<<(n + 31) / 32, 64>>>(nullptr, W2, n);
    k_att<2><<<(n + 7) / 8, 256>>>(a2s, a2d, n);
    k_edge_max<2><<<(E + 255) / 256, 256>>>(E);
    k_selfinit<2><<<(n + 7) / 8, 256>>>(n);
    k_scatter<2><<<(E + 15) / 16, 256>>>(E);
    k_fin2<<<(n + 7) / 8, 256>>>(b2, out, n);
}